// round 9
// baseline (speedup 1.0000x reference)
#include <cuda_runtime.h>
#include <math.h>

#define HID 1024
#define VOC 50257
#define SEQ 512
#define N4  12564   // floor(VOC/4); element VOC-1 handled scalar

__device__ __align__(16) float g_alog[SEQ];        // attention logits
__device__ __align__(16) float g_w[SEQ];           // softmax weights
__device__ __align__(16) float g_papp[4 * HID];    // partial attn_applied (4 i-chunks)
__device__ __align__(16) float g_x[HID];           // relu(comb) output
__device__ __align__(16) float g_h[HID];           // h_new (aligned copy for k_out)
__device__ __align__(16) float g_gih[6 * HID];     // [gi_r gi_z gi_n gh_r gh_z gh_n]
__device__ __align__(16) float g_logits[VOC + 3];  // padded for float4
__device__ float g_red[2];                         // max, log(sum exp)
__device__ int   g_ctr1, g_ctr2, g_ctr3;

__device__ __forceinline__ float wsum(float v) {
#pragma unroll
    for (int o = 16; o; o >>= 1) v += __shfl_xor_sync(0xffffffffu, v, o);
    return v;
}
__device__ __forceinline__ float wmax(float v) {
#pragma unroll
    for (int o = 16; o; o >>= 1) v = fmaxf(v, __shfl_xor_sync(0xffffffffu, v, o));
    return v;
}
__device__ __forceinline__ float dot4(float4 a, float4 b) {
    return a.x * b.x + a.y * b.y + a.z * b.z + a.w * b.w;
}

// K1: blocks [0,128): attn logits, 1 row/warp over full 2048 cols (+softmax tail).
//     blocks [128,320): gh = W_hh @ h0, 4 rows/warp.  No smem staging anywhere.
__global__ void __launch_bounds__(128, 4)
k_attn_gh(const int* __restrict__ tok, const float* __restrict__ hid,
          const float* __restrict__ emb, const float* __restrict__ attn_W,
          const float* __restrict__ attn_b, const float* __restrict__ W_hh,
          float* __restrict__ out_attn) {
    int t = threadIdx.x, w = t >> 5, lane = t & 31;

    if (blockIdx.x >= 128) {
        // ---- gh: rows r0..r0+3 of W_hh ----
        int r0 = (blockIdx.x - 128) * 16 + w * 4;
        const float4* hv = (const float4*)hid;
        const float4* m0 = (const float4*)(W_hh + (long)r0 * HID);
        const float4* m1 = (const float4*)(W_hh + (long)(r0 + 1) * HID);
        const float4* m2 = (const float4*)(W_hh + (long)(r0 + 2) * HID);
        const float4* m3 = (const float4*)(W_hh + (long)(r0 + 3) * HID);
        float s0 = 0.f, s1 = 0.f, s2 = 0.f, s3 = 0.f;
#pragma unroll
        for (int i = 0; i < 8; i++) {
            int k = lane + 32 * i;
            float4 b = __ldg(hv + k);
            s0 += dot4(__ldcs(m0 + k), b);
            s1 += dot4(__ldcs(m1 + k), b);
            s2 += dot4(__ldcs(m2 + k), b);
            s3 += dot4(__ldcs(m3 + k), b);
        }
        s0 = wsum(s0); s1 = wsum(s1); s2 = wsum(s2); s3 = wsum(s3);
        if (lane == 0) {
            g_gih[3 * HID + r0]     = s0;
            g_gih[3 * HID + r0 + 1] = s1;
            g_gih[3 * HID + r0 + 2] = s2;
            g_gih[3 * HID + r0 + 3] = s3;
        }
        return;
    }

    // ---- attn logits: 1 row/warp ----
    int row = blockIdx.x * 4 + w;
    const float4* m  = (const float4*)(attn_W + (long)row * 2 * HID);
    const float4* ev = (const float4*)(emb + (long)tok[0] * HID);
    const float4* hv = (const float4*)hid;
    float s = 0.f;
#pragma unroll
    for (int i = 0; i < 8; i++) {
        int k = lane + 32 * i;
        s += dot4(__ldcs(m + k), __ldg(ev + k));
    }
#pragma unroll
    for (int i = 0; i < 8; i++) {
        int k = lane + 32 * i;
        s += dot4(__ldcs(m + 256 + k), __ldg(hv + k));
    }
    s = wsum(s);
    if (lane == 0) {
        g_alog[row] = s + attn_b[row];
        __threadfence();
    }
    __shared__ int s_last;
    __syncthreads();
    if (t == 0) s_last = (atomicAdd(&g_ctr1, 1) == 127);
    __syncthreads();
    if (!s_last) return;
    // ---- last attn block: softmax over 512 (128 threads, 4 vals each) ----
    __threadfence();
    if (t == 0) g_ctr1 = 0;
    __shared__ float red[4];
    __shared__ float bcM, bcS;
    float v0 = g_alog[t], v1 = g_alog[t + 128], v2 = g_alog[t + 256], v3 = g_alog[t + 384];
    float mx = wmax(fmaxf(fmaxf(v0, v1), fmaxf(v2, v3)));
    if (lane == 0) red[w] = mx;
    __syncthreads();
    if (t == 0) bcM = fmaxf(fmaxf(red[0], red[1]), fmaxf(red[2], red[3]));
    __syncthreads();
    float e0 = __expf(v0 - bcM), e1 = __expf(v1 - bcM);
    float e2 = __expf(v2 - bcM), e3 = __expf(v3 - bcM);
    float ss = wsum(e0 + e1 + e2 + e3);
    if (lane == 0) red[w] = ss;
    __syncthreads();
    if (t == 0) bcS = red[0] + red[1] + red[2] + red[3];
    __syncthreads();
    float inv = 1.f / bcS;
    float w0 = e0 * inv, w1 = e1 * inv, w2 = e2 * inv, w3 = e3 * inv;
    g_w[t] = w0; g_w[t + 128] = w1; g_w[t + 256] = w2; g_w[t + 384] = w3;
    out_attn[t] = w0; out_attn[t + 128] = w1; out_attn[t + 256] = w2; out_attn[t + 384] = w3;
}

// K2: partial attn_applied. 16 blocks = 4 j-blocks x 4 i-chunks (no atomics).
__global__ void __launch_bounds__(256, 2) k_app(const float* __restrict__ enc) {
    int t = threadIdx.x;
    __shared__ float w[128];
    int jb = blockIdx.x & 3, ic = blockIdx.x >> 2;
    if (t < 128) w[t] = g_w[ic * 128 + t];
    __syncthreads();
    int j = jb * 256 + t;
    const float* ep = enc + (long)ic * 128 * HID + j;
    float acc = 0.f;
#pragma unroll 16
    for (int i = 0; i < 128; i++) acc += w[i] * __ldcs(ep + (long)i * HID);
    g_papp[ic * HID + j] = acc;
}

// K3: x = relu([embed, attn_applied] @ comb_W.T + b). 1 row/warp, 256 blocks x 128.
__global__ void __launch_bounds__(128, 4)
k_comb(const int* __restrict__ tok, const float* __restrict__ emb,
       const float* __restrict__ comb_W, const float* __restrict__ comb_b) {
    int t = threadIdx.x, w = t >> 5, lane = t & 31;
    int row = blockIdx.x * 4 + w;
    const float4* m  = (const float4*)(comb_W + (long)row * 2 * HID);
    const float4* ev = (const float4*)(emb + (long)tok[0] * HID);
    const float4* p0 = (const float4*)(g_papp + 0 * HID);
    const float4* p1 = (const float4*)(g_papp + 1 * HID);
    const float4* p2 = (const float4*)(g_papp + 2 * HID);
    const float4* p3 = (const float4*)(g_papp + 3 * HID);
    float s = 0.f;
#pragma unroll
    for (int i = 0; i < 8; i++) {
        int k = lane + 32 * i;
        s += dot4(__ldcs(m + k), __ldg(ev + k));
    }
#pragma unroll
    for (int i = 0; i < 8; i++) {
        int k = lane + 32 * i;
        float4 a = __ldcs(m + 256 + k);
        float4 q0 = __ldg(p0 + k), q1 = __ldg(p1 + k);
        float4 q2 = __ldg(p2 + k), q3 = __ldg(p3 + k);
        s += a.x * (q0.x + q1.x + q2.x + q3.x)
           + a.y * (q0.y + q1.y + q2.y + q3.y)
           + a.z * (q0.z + q1.z + q2.z + q3.z)
           + a.w * (q0.w + q1.w + q2.w + q3.w);
    }
    s = wsum(s);
    if (lane == 0) g_x[row] = fmaxf(s + comb_b[row], 0.f);
}

// K4: gi = W_ih @ x (3072 rows, 4 rows/warp, 192 blocks x 128) + gate tail.
__global__ void __launch_bounds__(128, 4)
k_gi(const float* __restrict__ hid, const float* __restrict__ W_ih,
     const float* __restrict__ b_ih, const float* __restrict__ b_hh,
     float* __restrict__ out_h) {
    int t = threadIdx.x, w = t >> 5, lane = t & 31;
    int r0 = blockIdx.x * 16 + w * 4;
    const float4* xv = (const float4*)g_x;
    const float4* m0 = (const float4*)(W_ih + (long)r0 * HID);
    const float4* m1 = (const float4*)(W_ih + (long)(r0 + 1) * HID);
    const float4* m2 = (const float4*)(W_ih + (long)(r0 + 2) * HID);
    const float4* m3 = (const float4*)(W_ih + (long)(r0 + 3) * HID);
    float s0 = 0.f, s1 = 0.f, s2 = 0.f, s3 = 0.f;
#pragma unroll
    for (int i = 0; i < 8; i++) {
        int k = lane + 32 * i;
        float4 b = __ldg(xv + k);
        s0 += dot4(__ldcs(m0 + k), b);
        s1 += dot4(__ldcs(m1 + k), b);
        s2 += dot4(__ldcs(m2 + k), b);
        s3 += dot4(__ldcs(m3 + k), b);
    }
    s0 = wsum(s0); s1 = wsum(s1); s2 = wsum(s2); s3 = wsum(s3);
    if (lane == 0) {
        g_gih[r0] = s0; g_gih[r0 + 1] = s1; g_gih[r0 + 2] = s2; g_gih[r0 + 3] = s3;
        __threadfence();
    }
    __shared__ int s_last;
    __syncthreads();
    if (t == 0) s_last = (atomicAdd(&g_ctr2, 1) == (int)gridDim.x - 1);
    __syncthreads();
    if (!s_last) return;
    // ---- last block: gate math; write h_new to out AND to aligned g_h ----
    __threadfence();
    if (t == 0) g_ctr2 = 0;
    for (int j = t; j < HID; j += 128) {
        float ir  = g_gih[j]           + b_ih[j];
        float iz  = g_gih[HID + j]     + b_ih[HID + j];
        float in_ = g_gih[2 * HID + j] + b_ih[2 * HID + j];
        float hr  = g_gih[3 * HID + j] + b_hh[j];
        float hz  = g_gih[4 * HID + j] + b_hh[HID + j];
        float hn  = g_gih[5 * HID + j] + b_hh[2 * HID + j];
        float r = 1.f / (1.f + __expf(-(ir + hr)));
        float z = 1.f / (1.f + __expf(-(iz + hz)));
        float n = tanhf(in_ + r * hn);
        float hv = (1.f - z) * n + z * hid[j];
        out_h[j] = hv;
        g_h[j]   = hv;
    }
}

// K5: logits = h_new @ out_W.T + out_b (206 MB; 4 rows/warp, 3142 blocks x 128)
//     + logsumexp tail in elected last block.  Vector read from aligned g_h.
__global__ void __launch_bounds__(128, 4)
k_out(const float* __restrict__ out_W, const float* __restrict__ out_b) {
    int t = threadIdx.x, w = t >> 5, lane = t & 31;
    int r0 = blockIdx.x * 16 + w * 4;
    if (r0 < VOC) {
        int r1 = min(r0 + 1, VOC - 1);
        int r2 = min(r0 + 2, VOC - 1);
        int r3 = min(r0 + 3, VOC - 1);
        const float4* hv = (const float4*)g_h;
        const float4* m0 = (const float4*)(out_W + (long)r0 * HID);
        const float4* m1 = (const float4*)(out_W + (long)r1 * HID);
        const float4* m2 = (const float4*)(out_W + (long)r2 * HID);
        const float4* m3 = (const float4*)(out_W + (long)r3 * HID);
        float s0 = 0.f, s1 = 0.f, s2 = 0.f, s3 = 0.f;
#pragma unroll
        for (int i = 0; i < 8; i++) {
            int k = lane + 32 * i;
            float4 b = __ldg(hv + k);
            s0 += dot4(__ldcs(m0 + k), b);
            s1 += dot4(__ldcs(m1 + k), b);
            s2 += dot4(__ldcs(m2 + k), b);
            s3 += dot4(__ldcs(m3 + k), b);
        }
        s0 = wsum(s0); s1 = wsum(s1); s2 = wsum(s2); s3 = wsum(s3);
        if (lane == 0) {
            g_logits[r0] = s0 + out_b[r0];
            if (r0 + 1 < VOC) g_logits[r0 + 1] = s1 + out_b[r0 + 1];
            if (r0 + 2 < VOC) g_logits[r0 + 2] = s2 + out_b[r0 + 2];
            if (r0 + 3 < VOC) g_logits[r0 + 3] = s3 + out_b[r0 + 3];
            __threadfence();
        }
    }
    __shared__ int s_last;
    __syncthreads();
    if (t == 0) s_last = (atomicAdd(&g_ctr3, 1) == (int)gridDim.x - 1);
    __syncthreads();
    if (!s_last) return;
    // ---- last block: online logsumexp over logits (L2-resident) ----
    __threadfence();
    if (t == 0) g_ctr3 = 0;
    __shared__ float shm[4], shs[4];
    const float4* L4 = (const float4*)g_logits;
    float m = -1e30f, s = 0.f;
    for (int i = t; i < N4; i += 128) {
        float4 v = L4[i];
        float lm = fmaxf(fmaxf(v.x, v.y), fmaxf(v.z, v.w));
        if (lm > m) { s = s * __expf(m - lm); m = lm; }
        s += __expf(v.x - m) + __expf(v.y - m) + __expf(v.z - m) + __expf(v.w - m);
    }
    if (t == 0) {
        float v = g_logits[VOC - 1];
        if (v > m) { s = s * __expf(m - v); m = v; }
        s += __expf(v - m);
    }
#pragma unroll
    for (int o = 16; o; o >>= 1) {
        float om = __shfl_xor_sync(0xffffffffu, m, o);
        float os = __shfl_xor_sync(0xffffffffu, s, o);
        if (om > m) { s = s * __expf(m - om) + os; m = om; }
        else          s += os * __expf(om - m);
    }
    if (lane == 0) { shm[w] = m; shs[w] = s; }
    __syncthreads();
    if (t == 0) {
        float M = shm[0], S = shs[0];
        for (int i = 1; i < 4; i++) {
            float om = shm[i], os = shs[i];
            if (om > M) { S = S * __expf(M - om) + os; M = om; }
            else          S += os * __expf(om - M);
        }
        g_red[0] = M; g_red[1] = logf(S);
    }
}

// K6: logp = logits - (max + logsum)   (13 blocks x 1024, float4)
__global__ void __launch_bounds__(1024) k_logp(float* __restrict__ out) {
    float off = g_red[0] + g_red[1];
    int i = blockIdx.x * 1024 + threadIdx.x;
    if (i < N4) {
        float4 v = ((const float4*)g_logits)[i];
        v.x -= off; v.y -= off; v.z -= off; v.w -= off;
        ((float4*)out)[i] = v;
    }
    if (i == 0) out[VOC - 1] = g_logits[VOC - 1] - off;
}

extern "C" void kernel_launch(void* const* d_in, const int* in_sizes, int n_in,
                              void* d_out, int out_size) {
    const int*   tok    = (const int*)d_in[0];
    const float* hidden = (const float*)d_in[1];
    const float* enc    = (const float*)d_in[2];
    const float* emb    = (const float*)d_in[3];
    const float* attn_W = (const float*)d_in[4];
    const float* attn_b = (const float*)d_in[5];
    const float* comb_W = (const float*)d_in[6];
    const float* comb_b = (const float*)d_in[7];
    const float* W_ih   = (const float*)d_in[8];
    const float* W_hh   = (const float*)d_in[9];
    const float* b_ih   = (const float*)d_in[10];
    const float* b_hh   = (const float*)d_in[11];
    const float* out_W  = (const float*)d_in[12];
    const float* out_b  = (const float*)d_in[13];

    float* out      = (float*)d_out;         // logp  [50257]
    float* out_h    = out + VOC;             // h_new [1024]  (NOT 16B-aligned!)
    float* out_attn = out + VOC + HID;       // attn_weights [512]

    k_attn_gh<<<320, 128>>>(tok, hidden, emb, attn_W, attn_b, W_hh, out_attn);
    k_app<<<16, 256>>>(enc);
    k_comb<<<256, 128>>>(tok, emb, comb_W, comb_b);
    k_gi<<<192, 128>>>(hidden, W_ih, b_ih, b_hh, out_h);
    k_out<<<(VOC + 15) / 16, 128>>>(out_W, out_b);
    k_logp<<<(N4 + 1023) / 1024, 1024>>>(out);
}